// round 3
// baseline (speedup 1.0000x reference)
#include <cuda_runtime.h>
#include <math.h>

// ---------------------------------------------------------------------------
// PairwiseAttention: z(1,256,256,128) -> LN -> QKV -> 4-head attn -> proj -> +z
// Round 2: fp32 with packed fma.rn.f32x2 (sm_10x FFMA2) in all MAC loops.
// FFMA-pipe-bound by model; f32x2 doubles the MAC rate on that pipe.
// ---------------------------------------------------------------------------

#define L 256
#define D 128
#define NH 4
#define HD 32
#define M_TOTAL (L * L)          // 65536 positions
#define QKV_N (3 * D)            // 384

typedef unsigned long long ull;

// Scratch (alloc-free rule: __device__ globals)
__device__ float g_zn[M_TOTAL * D];        //  33.5 MB
__device__ float g_qkv[(size_t)M_TOTAL * QKV_N];   // 100.7 MB
__device__ float g_attn[M_TOTAL * D];      //  33.5 MB

// ---- packed f32x2 helpers (sm_100+) ---------------------------------------
__device__ __forceinline__ void fma2(ull& d, ull a, ull b) {
    asm("fma.rn.f32x2 %0, %1, %2, %0;" : "+l"(d) : "l"(a), "l"(b));
}
__device__ __forceinline__ ull add2(ull a, ull b) {
    ull r; asm("add.rn.f32x2 %0, %1, %2;" : "=l"(r) : "l"(a), "l"(b)); return r;
}
__device__ __forceinline__ ull mul2(ull a, ull b) {
    ull r; asm("mul.rn.f32x2 %0, %1, %2;" : "=l"(r) : "l"(a), "l"(b)); return r;
}
__device__ __forceinline__ ull pack2(float x, float y) {
    ull r; asm("mov.b64 %0, {%1, %2};" : "=l"(r) : "f"(x), "f"(y)); return r;
}
__device__ __forceinline__ float2 unpack2(ull v) {
    float2 r; asm("mov.b64 {%0, %1}, %2;" : "=f"(r.x), "=f"(r.y) : "l"(v)); return r;
}

// ---------------------------------------------------------------------------
// Kernel 1: LayerNorm. One warp per position (128 values = 4 per lane).
// ---------------------------------------------------------------------------
__global__ void ln_kernel(const float* __restrict__ z,
                          const float* __restrict__ g,
                          const float* __restrict__ b) {
    int pos  = blockIdx.x * 8 + (threadIdx.x >> 5);
    int lane = threadIdx.x & 31;
    const float* zp = z + (size_t)pos * D;

    float4 v = *(const float4*)&zp[lane * 4];
    float s = v.x + v.y + v.z + v.w;
    #pragma unroll
    for (int o = 16; o; o >>= 1) s += __shfl_xor_sync(0xffffffffu, s, o);
    float mu = s * (1.0f / 128.0f);

    float dx = v.x - mu, dy = v.y - mu, dz = v.z - mu, dw = v.w - mu;
    float q = dx * dx + dy * dy + dz * dz + dw * dw;
    #pragma unroll
    for (int o = 16; o; o >>= 1) q += __shfl_xor_sync(0xffffffffu, q, o);
    float rstd = rsqrtf(q * (1.0f / 128.0f) + 1e-5f);

    float4 gg = *(const float4*)&g[lane * 4];
    float4 bb = *(const float4*)&b[lane * 4];
    float4 o4;
    o4.x = dx * rstd * gg.x + bb.x;
    o4.y = dy * rstd * gg.y + bb.y;
    o4.z = dz * rstd * gg.z + bb.z;
    o4.w = dw * rstd * gg.w + bb.w;
    *(float4*)&g_zn[(size_t)pos * D + lane * 4] = o4;
}

// ---------------------------------------------------------------------------
// GEMM body: C[M x N] = A[M x 128] @ B[128 x N] + bias (+ Zr residual).
// 128x128 block tile, 256 threads, 8x8 outputs/thread, packed f32x2 FMA.
// K staged in 4 chunks of 32. A transposed in smem for packed-n B reads.
// ---------------------------------------------------------------------------
__device__ __forceinline__ void gemm_body(const float* __restrict__ A,
                                          const float* __restrict__ B,
                                          const float* __restrict__ bias,
                                          const float* __restrict__ Zr,
                                          float* __restrict__ C,
                                          int N, bool resid) {
    __shared__ float As[32][132];   // As[k][m], pad 4 (row = 528B, 16B-aligned)
    __shared__ float Bs[32][128];   // Bs[k][n]

    int tid = threadIdx.x;
    int m0 = blockIdx.y * 128;
    int n0 = blockIdx.x * 128;
    int ty = tid >> 4;             // 0..15: rows ty*8..+7
    int tx = tid & 15;             // 0..15: cols tx*8..+7

    ull acc[8][4];
    #pragma unroll
    for (int i = 0; i < 8; i++)
        #pragma unroll
        for (int j = 0; j < 4; j++) acc[i][j] = 0ull;   // = (0.0f, 0.0f)

    #pragma unroll
    for (int kc = 0; kc < D; kc += 32) {
        // A tile: 128 rows x 32 k, stored transposed. 1024 float4-units.
        #pragma unroll
        for (int i = 0; i < 4; i++) {
            int idx = tid + i * 256;
            int row = idx >> 3, k4 = idx & 7;
            float4 a = *(const float4*)&A[(size_t)(m0 + row) * D + kc + k4 * 4];
            As[k4 * 4 + 0][row] = a.x;
            As[k4 * 4 + 1][row] = a.y;
            As[k4 * 4 + 2][row] = a.z;
            As[k4 * 4 + 3][row] = a.w;
        }
        // B tile: 32 k x 128 n.
        #pragma unroll
        for (int i = 0; i < 4; i++) {
            int idx = tid + i * 256;
            int k = idx >> 5, n4 = idx & 31;
            *(float4*)&Bs[k][n4 * 4] =
                *(const float4*)&B[(size_t)(kc + k) * N + n0 + n4 * 4];
        }
        __syncthreads();

        #pragma unroll
        for (int k = 0; k < 32; k++) {
            float4 a0 = *(const float4*)&As[k][ty * 8];
            float4 a1 = *(const float4*)&As[k][ty * 8 + 4];
            ulonglong2 b0 = *(const ulonglong2*)&Bs[k][tx * 8];
            ulonglong2 b1 = *(const ulonglong2*)&Bs[k][tx * 8 + 4];
            ull bb0 = b0.x, bb1 = b0.y, bb2 = b1.x, bb3 = b1.y;
            float av[8] = {a0.x, a0.y, a0.z, a0.w, a1.x, a1.y, a1.z, a1.w};
            #pragma unroll
            for (int i = 0; i < 8; i++) {
                ull ai = pack2(av[i], av[i]);
                fma2(acc[i][0], ai, bb0);
                fma2(acc[i][1], ai, bb1);
                fma2(acc[i][2], ai, bb2);
                fma2(acc[i][3], ai, bb3);
            }
        }
        __syncthreads();
    }

    float4 bi0 = *(const float4*)&bias[n0 + tx * 8];
    float4 bi1 = *(const float4*)&bias[n0 + tx * 8 + 4];
    float bv[8] = {bi0.x, bi0.y, bi0.z, bi0.w, bi1.x, bi1.y, bi1.z, bi1.w};

    #pragma unroll
    for (int i = 0; i < 8; i++) {
        int row = m0 + ty * 8 + i;
        float2 p0 = unpack2(acc[i][0]);
        float2 p1 = unpack2(acc[i][1]);
        float2 p2 = unpack2(acc[i][2]);
        float2 p3 = unpack2(acc[i][3]);
        float o[8] = {p0.x + bv[0], p0.y + bv[1], p1.x + bv[2], p1.y + bv[3],
                      p2.x + bv[4], p2.y + bv[5], p3.x + bv[6], p3.y + bv[7]};
        if (resid) {
            const float* zr = &Zr[(size_t)row * N + n0 + tx * 8];
            #pragma unroll
            for (int j = 0; j < 8; j++) o[j] += zr[j];
        }
        float* cp = &C[(size_t)row * N + n0 + tx * 8];
        *(float4*)&cp[0] = make_float4(o[0], o[1], o[2], o[3]);
        *(float4*)&cp[4] = make_float4(o[4], o[5], o[6], o[7]);
    }
}

__global__ void gemm_qkv_kernel(const float* __restrict__ B,
                                const float* __restrict__ bias) {
    gemm_body(g_zn, B, bias, nullptr, g_qkv, QKV_N, false);
}

__global__ void gemm_proj_kernel(const float* __restrict__ B,
                                 const float* __restrict__ bias,
                                 const float* __restrict__ z,
                                 float* __restrict__ C) {
    gemm_body(g_attn, B, bias, z, C, D, true);
}

// ---------------------------------------------------------------------------
// Kernel 3: attention. Grid (h=4, r=256). 256 threads = one per query.
// K/V tiled in smem, online softmax, packed f32x2 for QK dots and AV accum.
// ---------------------------------------------------------------------------
__global__ void attn_kernel() {
    __shared__ float ks[128][HD];
    __shared__ float vs[128][HD];

    int h = blockIdx.x;
    int r = blockIdx.y;
    int tid = threadIdx.x;
    const float* base = g_qkv + (size_t)r * L * QKV_N;

    // Query: 32 floats = 16 packed pairs.
    ull q2[16];
    const float* qp = base + (size_t)tid * QKV_N + h * HD;
    #pragma unroll
    for (int i = 0; i < 8; i++) {
        ulonglong2 t = *(const ulonglong2*)&qp[i * 4];
        q2[i * 2 + 0] = t.x;
        q2[i * 2 + 1] = t.y;
    }

    const float scale = 0.17677669529663687f;  // 1/sqrt(32)
    float m = -1e30f, l = 0.0f;
    ull acc2[16];
    #pragma unroll
    for (int p = 0; p < 16; p++) acc2[p] = 0ull;

    #pragma unroll 1
    for (int kt = 0; kt < 2; kt++) {
        __syncthreads();
        #pragma unroll
        for (int i = 0; i < 4; i++) {
            int idx = tid + i * 256;
            int j = idx >> 3, c4 = idx & 7;
            const float* kp = base + (size_t)(kt * 128 + j) * QKV_N + D + h * HD;
            *(float4*)&ks[j][c4 * 4] = *(const float4*)&kp[c4 * 4];
            *(float4*)&vs[j][c4 * 4] = *(const float4*)&kp[D + c4 * 4];
        }
        __syncthreads();

        #pragma unroll 2
        for (int j = 0; j < 128; j++) {
            // QK dot: 16 packed fma into 4 packed partials.
            ull s2[4] = {0ull, 0ull, 0ull, 0ull};
            const ulonglong2* kp2 = (const ulonglong2*)&ks[j][0];
            #pragma unroll
            for (int p = 0; p < 8; p++) {
                ulonglong2 kk = kp2[p];
                fma2(s2[(2 * p) & 3], q2[2 * p], kk.x);
                fma2(s2[(2 * p + 1) & 3], q2[2 * p + 1], kk.y);
            }
            ull u = add2(add2(s2[0], s2[1]), add2(s2[2], s2[3]));
            float2 uf = unpack2(u);
            float s = (uf.x + uf.y) * scale;

            if (s > m) {
                float corr = __expf(m - s);
                m = s;
                l *= corr;
                ull c2 = pack2(corr, corr);
                #pragma unroll
                for (int p = 0; p < 16; p++) acc2[p] = mul2(acc2[p], c2);
            }
            float e = __expf(s - m);
            l += e;
            ull e2 = pack2(e, e);
            const ulonglong2* vp2 = (const ulonglong2*)&vs[j][0];
            #pragma unroll
            for (int p = 0; p < 8; p++) {
                ulonglong2 vv = vp2[p];
                fma2(acc2[2 * p + 0], e2, vv.x);
                fma2(acc2[2 * p + 1], e2, vv.y);
            }
        }
    }

    float inv = 1.0f / l;
    float* op = g_attn + ((size_t)r * L + tid) * D + h * HD;
    #pragma unroll
    for (int p = 0; p < 8; p++) {
        float2 a = unpack2(acc2[2 * p]);
        float2 b = unpack2(acc2[2 * p + 1]);
        *(float4*)&op[p * 4] = make_float4(a.x * inv, a.y * inv, b.x * inv, b.y * inv);
    }
}

// ---------------------------------------------------------------------------
// Launch: 4 kernels, default stream, graph-capturable, no allocs.
// ---------------------------------------------------------------------------
extern "C" void kernel_launch(void* const* d_in, const int* in_sizes, int n_in,
                              void* d_out, int out_size) {
    const float* z      = (const float*)d_in[0];
    const float* ln_g   = (const float*)d_in[1];
    const float* ln_b   = (const float*)d_in[2];
    const float* w_qkv  = (const float*)d_in[3];
    const float* b_qkv  = (const float*)d_in[4];
    const float* w_proj = (const float*)d_in[5];
    const float* b_proj = (const float*)d_in[6];
    float* out = (float*)d_out;

    ln_kernel<<<M_TOTAL / 8, 256>>>(z, ln_g, ln_b);
    gemm_qkv_kernel<<<dim3(QKV_N / 128, M_TOTAL / 128), 256>>>(w_qkv, b_qkv);
    attn_kernel<<<dim3(NH, L), 256>>>();
    gemm_proj_kernel<<<dim3(D / 128, M_TOTAL / 128), 256>>>(w_proj, b_proj, z, out);
}

// round 5
// speedup vs baseline: 2.6077x; 2.6077x over previous
#include <cuda_runtime.h>
#include <cuda_bf16.h>
#include <math.h>
#include <stdint.h>

// ---------------------------------------------------------------------------
// PairwiseAttention: z(1,256,256,128) -> LN -> QKV -> 4-head attn -> proj -> +z
// Round 4: same design as round 3 (HMMA bf16 hi/lo split, FA2 fused attention),
// with all host-side symbol-address lookups removed (kernels use the
// __device__ globals directly) to minimize graph-capture surface.
// ---------------------------------------------------------------------------

#define L 256
#define D 128
#define NH 4
#define HD 32
#define M_TOTAL (L * L)          // 65536
#define QKV_N (3 * D)            // 384

// Scratch (__device__ globals; no allocations allowed)
__device__ __nv_bfloat16 g_znh[(size_t)M_TOTAL * D];
__device__ __nv_bfloat16 g_znl[(size_t)M_TOTAL * D];
__device__ float         g_qkv[(size_t)M_TOTAL * QKV_N];
__device__ float         g_attn[(size_t)M_TOTAL * D];
__device__ __nv_bfloat16 g_wqh[D * QKV_N], g_wql[D * QKV_N];
__device__ __nv_bfloat16 g_wph[D * D],     g_wpl[D * D];

// ---- helpers --------------------------------------------------------------
__device__ __forceinline__ uint32_t smem_u32(const void* p) {
    return (uint32_t)__cvta_generic_to_shared(p);
}
__device__ __forceinline__ void ldmx4(uint32_t* r, uint32_t a) {
    asm volatile("ldmatrix.sync.aligned.m8n8.x4.shared.b16 {%0,%1,%2,%3}, [%4];"
                 : "=r"(r[0]), "=r"(r[1]), "=r"(r[2]), "=r"(r[3]) : "r"(a));
}
__device__ __forceinline__ void ldmx4t(uint32_t* r, uint32_t a) {
    asm volatile("ldmatrix.sync.aligned.m8n8.x4.trans.shared.b16 {%0,%1,%2,%3}, [%4];"
                 : "=r"(r[0]), "=r"(r[1]), "=r"(r[2]), "=r"(r[3]) : "r"(a));
}
__device__ __forceinline__ void mma16816(float* d, const uint32_t* a, const uint32_t* b) {
    asm volatile(
        "mma.sync.aligned.m16n8k16.row.col.f32.bf16.bf16.f32 "
        "{%0,%1,%2,%3}, {%4,%5,%6,%7}, {%8,%9}, {%0,%1,%2,%3};"
        : "+f"(d[0]), "+f"(d[1]), "+f"(d[2]), "+f"(d[3])
        : "r"(a[0]), "r"(a[1]), "r"(a[2]), "r"(a[3]), "r"(b[0]), "r"(b[1]));
}
// split v -> hi (bf16) and lo = v - float(hi) (bf16)
__device__ __forceinline__ void split1(float v, __nv_bfloat16& h, __nv_bfloat16& l) {
    h = __float2bfloat16_rn(v);
    l = __float2bfloat16_rn(v - __bfloat162float(h));
}
__device__ __forceinline__ void split4(float4 v, uint2& hi, uint2& lo) {
    __nv_bfloat16 h0, h1, h2, h3, l0, l1, l2, l3;
    split1(v.x, h0, l0); split1(v.y, h1, l1);
    split1(v.z, h2, l2); split1(v.w, h3, l3);
    __nv_bfloat162 a = {h0, h1}, b = {h2, h3}, c = {l0, l1}, d = {l2, l3};
    hi.x = *(uint32_t*)&a; hi.y = *(uint32_t*)&b;
    lo.x = *(uint32_t*)&c; lo.y = *(uint32_t*)&d;
}

// ---------------------------------------------------------------------------
// Kernel: LayerNorm -> zn hi/lo bf16. One warp per position.
// ---------------------------------------------------------------------------
__global__ void ln_kernel(const float* __restrict__ z,
                          const float* __restrict__ g,
                          const float* __restrict__ b) {
    int pos  = blockIdx.x * 8 + (threadIdx.x >> 5);
    int lane = threadIdx.x & 31;
    const float* zp = z + (size_t)pos * D;

    float4 v = *(const float4*)&zp[lane * 4];
    float s = v.x + v.y + v.z + v.w;
    #pragma unroll
    for (int o = 16; o; o >>= 1) s += __shfl_xor_sync(0xffffffffu, s, o);
    float mu = s * (1.0f / 128.0f);

    float dx = v.x - mu, dy = v.y - mu, dz = v.z - mu, dw = v.w - mu;
    float q = dx * dx + dy * dy + dz * dz + dw * dw;
    #pragma unroll
    for (int o = 16; o; o >>= 1) q += __shfl_xor_sync(0xffffffffu, q, o);
    float rstd = rsqrtf(q * (1.0f / 128.0f) + 1e-5f);

    float4 gg = *(const float4*)&g[lane * 4];
    float4 bb = *(const float4*)&b[lane * 4];
    float4 o4;
    o4.x = dx * rstd * gg.x + bb.x;
    o4.y = dy * rstd * gg.y + bb.y;
    o4.z = dz * rstd * gg.z + bb.z;
    o4.w = dw * rstd * gg.w + bb.w;

    uint2 hi, lo;
    split4(o4, hi, lo);
    *(uint2*)&g_znh[(size_t)pos * D + lane * 4] = hi;
    *(uint2*)&g_znl[(size_t)pos * D + lane * 4] = lo;
}

// ---------------------------------------------------------------------------
// Kernel: split both fp32 weight matrices into bf16 hi/lo (one launch).
// n = D*QKV_N + D*D elements, first w_qkv then w_proj.
// ---------------------------------------------------------------------------
__global__ void splitw_kernel(const float* __restrict__ wq,
                              const float* __restrict__ wp) {
    int i = blockIdx.x * 256 + threadIdx.x;
    if (i < D * QKV_N) {
        __nv_bfloat16 h, l;
        split1(wq[i], h, l);
        g_wqh[i] = h; g_wql[i] = l;
    } else {
        int j = i - D * QKV_N;
        if (j < D * D) {
            __nv_bfloat16 h, l;
            split1(wp[j], h, l);
            g_wph[j] = h; g_wpl[j] = l;
        }
    }
}

// ---------------------------------------------------------------------------
// GEMM: C[M x N] = A[M x 128] @ B[128 x N] + bias (+ Zr residual)
// Block tile 128x128, 8 warps (2x4), warp tile 64x32, m16n8k16 bf16 x3 split.
// Dynamic smem 128 KB: Ah, Al [128][128], Bh, Bl [128][128] (swizzled).
// Swizzle: 16B chunk c (0..15) in a 256B row at row m -> c ^ (m & 7).
// MODE 0: QKV (A = g_zn hi/lo, B = g_wq, C = g_qkv, N=384)
// MODE 1: proj (A = g_attn fp32 split on the fly, B = g_wp, C = out, +z)
// ---------------------------------------------------------------------------
template<int MODE>
__global__ __launch_bounds__(256, 1)
void gemm_kernel(const float* __restrict__ bias,
                 const float* __restrict__ Zr,
                 float* __restrict__ Cout) {
    constexpr int N = (MODE == 0) ? QKV_N : D;
    extern __shared__ char sm_raw[];
    __nv_bfloat16* Ah = (__nv_bfloat16*)sm_raw;       // 128x128
    __nv_bfloat16* Al = Ah + 128 * 128;
    __nv_bfloat16* Bh = Al + 128 * 128;
    __nv_bfloat16* Bl = Bh + 128 * 128;

    int tid = threadIdx.x;
    int m0 = blockIdx.y * 128;
    int n0 = blockIdx.x * 128;

    // ---- stage A ----
    if (MODE == 1) {
        #pragma unroll
        for (int i = 0; i < 16; i++) {
            int idx = tid + i * 256;           // 4096 float4s
            int m = idx >> 5, gq = idx & 31, d = gq * 4;
            float4 v = *(const float4*)&g_attn[(size_t)(m0 + m) * D + d];
            uint2 hi, lo; split4(v, hi, lo);
            int c = d >> 3, sub = (d >> 2) & 1;
            int off = m * 128 + ((c ^ (m & 7)) * 8) + sub * 4;
            *(uint2*)&Ah[off] = hi;
            *(uint2*)&Al[off] = lo;
        }
    } else {
        #pragma unroll
        for (int i = 0; i < 8; i++) {
            int idx = tid + i * 256;           // 2048 16B-chunks
            int m = idx >> 4, c = idx & 15;
            uint4 vh = *(const uint4*)&g_znh[(size_t)(m0 + m) * D + c * 8];
            uint4 vl = *(const uint4*)&g_znl[(size_t)(m0 + m) * D + c * 8];
            int off = m * 128 + ((c ^ (m & 7)) * 8);
            *(uint4*)&Ah[off] = vh;
            *(uint4*)&Al[off] = vl;
        }
    }
    // ---- stage B ----
    {
        const __nv_bfloat16* Bhi_g = (MODE == 0) ? g_wqh : g_wph;
        const __nv_bfloat16* Blo_g = (MODE == 0) ? g_wql : g_wpl;
        #pragma unroll
        for (int i = 0; i < 8; i++) {
            int idx = tid + i * 256;
            int k = idx >> 4, c = idx & 15;
            uint4 vh = *(const uint4*)&Bhi_g[(size_t)k * N + n0 + c * 8];
            uint4 vl = *(const uint4*)&Blo_g[(size_t)k * N + n0 + c * 8];
            int off = k * 128 + ((c ^ (k & 7)) * 8);
            *(uint4*)&Bh[off] = vh;
            *(uint4*)&Bl[off] = vl;
        }
    }
    __syncthreads();

    int w = tid >> 5, l = tid & 31;
    int wm = w >> 2, wn = w & 3;
    int mw = wm * 64, nw = wn * 32;
    int sel = l >> 3, li = l & 7;

    uint32_t Abase = smem_u32(Ah);
    uint32_t Bbase = smem_u32(Bh);
    const uint32_t LOOFF = 128 * 128 * 2;   // bytes: hi array -> lo array

    float acc[4][4][4];
    #pragma unroll
    for (int mt = 0; mt < 4; mt++)
        #pragma unroll
        for (int nt = 0; nt < 4; nt++)
            #pragma unroll
            for (int j = 0; j < 4; j++) acc[mt][nt][j] = 0.0f;

    #pragma unroll
    for (int kt = 0; kt < 8; kt++) {
        uint32_t af[2][4][4];
        #pragma unroll
        for (int mt = 0; mt < 4; mt++) {
            int m = mw + mt * 16 + li + ((sel & 1) << 3);
            int kc = kt * 2 + (sel >> 1);
            uint32_t ad = Abase + (uint32_t)(m * 128 + ((kc ^ (m & 7)) * 8)) * 2;
            ldmx4(af[0][mt], ad);
            ldmx4(af[1][mt], ad + LOOFF);
        }
        uint32_t bf_[2][4][2];
        #pragma unroll
        for (int p = 0; p < 2; p++) {
            int k = kt * 16 + ((sel & 1) << 3) + li;
            int nc = (nw >> 3) + p * 2 + (sel >> 1);
            uint32_t bd = Bbase + (uint32_t)(k * 128 + ((nc ^ (k & 7)) * 8)) * 2;
            uint32_t t[4];
            ldmx4t(t, bd);
            bf_[0][2 * p][0] = t[0]; bf_[0][2 * p][1] = t[1];
            bf_[0][2 * p + 1][0] = t[2]; bf_[0][2 * p + 1][1] = t[3];
            ldmx4t(t, bd + LOOFF);
            bf_[1][2 * p][0] = t[0]; bf_[1][2 * p][1] = t[1];
            bf_[1][2 * p + 1][0] = t[2]; bf_[1][2 * p + 1][1] = t[3];
        }
        #pragma unroll
        for (int mt = 0; mt < 4; mt++)
            #pragma unroll
            for (int nt = 0; nt < 4; nt++) {
                mma16816(acc[mt][nt], af[0][mt], bf_[0][nt]);
                mma16816(acc[mt][nt], af[0][mt], bf_[1][nt]);
                mma16816(acc[mt][nt], af[1][mt], bf_[0][nt]);
            }
    }

    // ---- epilogue ----
    float* C = (MODE == 0) ? g_qkv : Cout;
    int grp = l >> 2, qd = l & 3;
    #pragma unroll
    for (int mt = 0; mt < 4; mt++) {
        #pragma unroll
        for (int nt = 0; nt < 4; nt++) {
            int gm = m0 + mw + mt * 16 + grp;
            int gn = n0 + nw + nt * 8 + qd * 2;
            float b0 = bias[gn], b1 = bias[gn + 1];
            float v0 = acc[mt][nt][0] + b0;
            float v1 = acc[mt][nt][1] + b1;
            float v2 = acc[mt][nt][2] + b0;
            float v3 = acc[mt][nt][3] + b1;
            if (MODE == 1) {
                float2 r0 = *(const float2*)&Zr[(size_t)gm * N + gn];
                float2 r1 = *(const float2*)&Zr[(size_t)(gm + 8) * N + gn];
                v0 += r0.x; v1 += r0.y; v2 += r1.x; v3 += r1.y;
            }
            *(float2*)&C[(size_t)gm * N + gn] = make_float2(v0, v1);
            *(float2*)&C[(size_t)(gm + 8) * N + gn] = make_float2(v2, v3);
        }
    }
}

// ---------------------------------------------------------------------------
// Attention: block per (h, r). 8 warps x 32 queries. Key tiles of 64,
// online softmax in C-fragments, P re-split to bf16 hi/lo in registers.
// smem 96 KB: Q, K, V each [256][64] bf16 (cols 0-31 = hi, 32-63 = lo),
// 128B rows, 16B chunk swizzle c ^ (row & 7).
// ---------------------------------------------------------------------------
__global__ __launch_bounds__(256, 1)
void attn_kernel() {
    extern __shared__ char sm_raw[];
    __nv_bfloat16* Qs = (__nv_bfloat16*)sm_raw;       // 256*64
    __nv_bfloat16* Ks = Qs + 256 * 64;
    __nv_bfloat16* Vs = Ks + 256 * 64;

    int h = blockIdx.x;
    int r = blockIdx.y;
    int tid = threadIdx.x;
    const float scale = 0.17677669529663687f;   // 1/sqrt(32)

    // ---- stage Q, K, V with on-the-fly split (Q pre-scaled) ----
    const float* srcbase = g_qkv + (size_t)r * L * QKV_N + h * HD;
    #pragma unroll
    for (int mat = 0; mat < 3; mat++) {
        __nv_bfloat16* dst = (mat == 0) ? Qs : (mat == 1) ? Ks : Vs;
        const float* src = srcbase + mat * D;
        float sc = (mat == 0) ? scale : 1.0f;
        #pragma unroll
        for (int i = 0; i < 8; i++) {
            int idx = tid + i * 256;            // 2048 float4s
            int key = idx >> 3, gq = idx & 7, d = gq * 4;
            float4 v = *(const float4*)&src[(size_t)key * QKV_N + d];
            v.x *= sc; v.y *= sc; v.z *= sc; v.w *= sc;
            uint2 hi, lo; split4(v, hi, lo);
            int sub = (d >> 2) & 1;
            int cH = d >> 3, cL = 4 + (d >> 3);
            *(uint2*)&dst[key * 64 + ((cH ^ (key & 7)) * 8) + sub * 4] = hi;
            *(uint2*)&dst[key * 64 + ((cL ^ (key & 7)) * 8) + sub * 4] = lo;
        }
    }
    __syncthreads();

    int w = tid >> 5, l = tid & 31;
    int q0 = w * 32;
    int sel = l >> 3, li = l & 7, grp = l >> 2, qd = l & 3;

    uint32_t Qbase = smem_u32(Qs);
    uint32_t Kbase = smem_u32(Ks);
    uint32_t Vbase = smem_u32(Vs);

    // Q fragments, kept resident: [split][kstep(2)][mtile(2)][4]
    uint32_t qf[2][2][2][4];
    #pragma unroll
    for (int spl = 0; spl < 2; spl++)
        #pragma unroll
        for (int kk = 0; kk < 2; kk++)
            #pragma unroll
            for (int mt = 0; mt < 2; mt++) {
                int m = q0 + mt * 16 + li + ((sel & 1) << 3);
                int kc = spl * 4 + kk * 2 + (sel >> 1);
                ldmx4(qf[spl][kk][mt],
                      Qbase + (uint32_t)(m * 64 + ((kc ^ (m & 7)) * 8)) * 2);
            }

    float mrow[2][2], lrow[2][2];
    float o[2][4][4];
    #pragma unroll
    for (int mt = 0; mt < 2; mt++)
        #pragma unroll
        for (int hf = 0; hf < 2; hf++) { mrow[mt][hf] = -1e30f; lrow[mt][hf] = 0.0f; }
    #pragma unroll
    for (int mt = 0; mt < 2; mt++)
        #pragma unroll
        for (int nt = 0; nt < 4; nt++)
            #pragma unroll
            for (int j = 0; j < 4; j++) o[mt][nt][j] = 0.0f;

    #pragma unroll 1
    for (int t = 0; t < 4; t++) {
        // ---- S = Q K^T (32 x 64) ----
        float s[2][8][4];
        #pragma unroll
        for (int mt = 0; mt < 2; mt++)
            #pragma unroll
            for (int nt = 0; nt < 8; nt++)
                #pragma unroll
                for (int j = 0; j < 4; j++) s[mt][nt][j] = 0.0f;

        #pragma unroll
        for (int kk = 0; kk < 2; kk++) {
            uint32_t kf[2][8][2];
            #pragma unroll
            for (int spl = 0; spl < 2; spl++)
                #pragma unroll
                for (int p = 0; p < 4; p++) {
                    int key = t * 64 + p * 16 + ((sel >> 1) << 3) + li;
                    int dc = spl * 4 + kk * 2 + (sel & 1);
                    uint32_t tr[4];
                    ldmx4(tr, Kbase + (uint32_t)(key * 64 + ((dc ^ (key & 7)) * 8)) * 2);
                    kf[spl][2 * p][0] = tr[0]; kf[spl][2 * p][1] = tr[1];
                    kf[spl][2 * p + 1][0] = tr[2]; kf[spl][2 * p + 1][1] = tr[3];
                }
            #pragma unroll
            for (int mt = 0; mt < 2; mt++)
                #pragma unroll
                for (int nt = 0; nt < 8; nt++) {
                    mma16816(s[mt][nt], qf[0][kk][mt], kf[0][nt]);
                    mma16816(s[mt][nt], qf[0][kk][mt], kf[1][nt]);
                    mma16816(s[mt][nt], qf[1][kk][mt], kf[0][nt]);
                }
        }

        // ---- online softmax ----
        #pragma unroll
        for (int mt = 0; mt < 2; mt++)
            #pragma unroll
            for (int hf = 0; hf < 2; hf++) {
                float tmax = -1e30f;
                #pragma unroll
                for (int nt = 0; nt < 8; nt++) {
                    tmax = fmaxf(tmax, s[mt][nt][2 * hf]);
                    tmax = fmaxf(tmax, s[mt][nt][2 * hf + 1]);
                }
                tmax = fmaxf(tmax, __shfl_xor_sync(0xffffffffu, tmax, 1));
                tmax = fmaxf(tmax, __shfl_xor_sync(0xffffffffu, tmax, 2));
                float mn = fmaxf(mrow[mt][hf], tmax);
                float corr = __expf(mrow[mt][hf] - mn);
                float ps = 0.0f;
                #pragma unroll
                for (int nt = 0; nt < 8; nt++) {
                    float e0 = __expf(s[mt][nt][2 * hf] - mn);
                    float e1 = __expf(s[mt][nt][2 * hf + 1] - mn);
                    s[mt][nt][2 * hf] = e0;
                    s[mt][nt][2 * hf + 1] = e1;
                    ps += e0 + e1;
                }
                ps += __shfl_xor_sync(0xffffffffu, ps, 1);
                ps += __shfl_xor_sync(0xffffffffu, ps, 2);
                lrow[mt][hf] = lrow[mt][hf] * corr + ps;
                mrow[mt][hf] = mn;
                #pragma unroll
                for (int nt = 0; nt < 4; nt++) {
                    o[mt][nt][2 * hf] *= corr;
                    o[mt][nt][2 * hf + 1] *= corr;
                }
            }

        // ---- O += P V ----
        #pragma unroll
        for (int kt = 0; kt < 4; kt++) {
            uint32_t pa[2][2][4];   // [split][mtile][4]
            #pragma unroll
            for (int mt = 0; mt < 2; mt++) {
                #pragma unroll
                for (int j = 0; j < 4; j++) {
                    int nt = 2 * kt + (j >> 1);
                    int c0 = (j & 1) * 2;
                    float x = s[mt][nt][c0], y = s[mt][nt][c0 + 1];
                    __nv_bfloat16 hx, lx, hy, ly;
                    split1(x, hx, lx);
                    split1(y, hy, ly);
                    __nv_bfloat162 ph = {hx, hy}, pl = {lx, ly};
                    pa[0][mt][j] = *(uint32_t*)&ph;
                    pa[1][mt][j] = *(uint32_t*)&pl;
                }
            }
            uint32_t vf[2][4][2];
            #pragma unroll
            for (int spl = 0; spl < 2; spl++)
                #pragma unroll
                for (int p = 0; p < 2; p++) {
                    int key = t * 64 + kt * 16 + ((sel & 1) << 3) + li;
                    int dc = spl * 4 + p * 2 + (sel >> 1);
                    uint32_t tr[4];
                    ldmx4t(tr, Vbase + (uint32_t)(key * 64 + ((dc ^ (key & 7)) * 8)) * 2);
                    vf[spl][2 * p][0] = tr[0]; vf[spl][2 * p][1] = tr[1];
                    vf[spl][2 * p + 1][0] = tr[2]; vf[spl][2 * p + 1][1] = tr[3];
                }
            #pragma unroll
            for (int mt = 0; mt < 2; mt++)
                #pragma unroll
                for (int nt = 0; nt < 4; nt++) {
                    mma16816(o[mt][nt], pa[0][mt], vf[0][nt]);
                    mma16816(o[mt][nt], pa[0][mt], vf[1][nt]);
                    mma16816(o[mt][nt], pa[1][mt], vf[0][nt]);
                }
        }
    }

    // ---- write O / l ----
    #pragma unroll
    for (int mt = 0; mt < 2; mt++) {
        float invA = 1.0f / lrow[mt][0];
        float invB = 1.0f / lrow[mt][1];
        #pragma unroll
        for (int nt = 0; nt < 4; nt++) {
            int q = q0 + mt * 16 + grp;
            int d = nt * 8 + qd * 2;
            float* op = g_attn + ((size_t)r * L + q) * D + h * HD + d;
            *(float2*)op = make_float2(o[mt][nt][0] * invA, o[mt][nt][1] * invA);
            float* op2 = op + 8 * D;
            *(float2*)op2 = make_float2(o[mt][nt][2] * invB, o[mt][nt][3] * invB);
        }
    }
}

// ---------------------------------------------------------------------------
// Launch
// ---------------------------------------------------------------------------
extern "C" void kernel_launch(void* const* d_in, const int* in_sizes, int n_in,
                              void* d_out, int out_size) {
    const float* z      = (const float*)d_in[0];
    const float* ln_g   = (const float*)d_in[1];
    const float* ln_b   = (const float*)d_in[2];
    const float* w_qkv  = (const float*)d_in[3];
    const float* b_qkv  = (const float*)d_in[4];
    const float* w_proj = (const float*)d_in[5];
    const float* b_proj = (const float*)d_in[6];
    float* out = (float*)d_out;

    const int GEMM_SMEM = 4 * 128 * 128 * 2;   // 131072 B
    const int ATTN_SMEM = 3 * 256 * 64 * 2;    //  98304 B
    cudaFuncSetAttribute(gemm_kernel<0>,
                         cudaFuncAttributeMaxDynamicSharedMemorySize, GEMM_SMEM);
    cudaFuncSetAttribute(gemm_kernel<1>,
                         cudaFuncAttributeMaxDynamicSharedMemorySize, GEMM_SMEM);
    cudaFuncSetAttribute(attn_kernel,
                         cudaFuncAttributeMaxDynamicSharedMemorySize, ATTN_SMEM);

    // 1) LN -> zn hi/lo
    ln_kernel<<<M_TOTAL / 8, 256>>>(z, ln_g, ln_b);
    // 2) weight splits (tiny)
    splitw_kernel<<<(D * QKV_N + D * D + 255) / 256, 256>>>(w_qkv, w_proj);
    // 3) QKV GEMM
    gemm_kernel<0><<<dim3(QKV_N / 128, M_TOTAL / 128), 256, GEMM_SMEM>>>(
        b_qkv, nullptr, nullptr);
    // 4) attention
    attn_kernel<<<dim3(NH, L), 256, ATTN_SMEM>>>();
    // 5) proj + bias + residual -> out
    gemm_kernel<1><<<dim3(1, M_TOTAL / 128), 256, GEMM_SMEM>>>(
        b_proj, z, out);
}